// round 7
// baseline (speedup 1.0000x reference)
#include <cuda_runtime.h>
#include <cuda_fp16.h>
#include <math.h>

// Problem constants: preds [8,4,256,256] f32, targets [8,256,256] i32.
#define B 8
#define H 256
#define W 256
#define NCLS 3              // classes 1..3
#define NCB 24              // cb = (cls-1)*8 + b
#define IMG 65536           // H*W
#define NPIX 524288         // B*H*W
#define RWIN 6              // window radius; certified exact when min <= 36
#define THRESH 36.0f
#define OOB 49.0f           // out-of-window / out-of-bounds distance^2 (>36)
#define TY 4                // rows of output per block
#define HR (TY + 2 * RWIN)  // halo rows per block = 16
#define NBLK2 512           // fused-kernel block count (8 b * 64 ytiles)

// -------- scratch (__device__ globals; no runtime allocation) --------
__device__ unsigned d_mask[NCLS * B * H * 8];  // row bitmasks (exact fallback)
__device__ int   d_flag[NCB * W];    // per (cb, x): window not certified
__device__ float d_partial[3 * NBLK2];
__device__ int   d_cnt[3 * NBLK2];

// ---------------------------------------------------------------------
// Branchless windowed row distance^2 (radius 6).
// win bits 0..12 correspond to positions x-6 .. x+6 (bit 6 = x).
// Exact for d <= 6, else 49 (>36, never enters a certified min).
// ---------------------------------------------------------------------
__device__ __forceinline__ int win_d2_6(unsigned win) {
    unsigned t = win & 0x7Fu;                 // x-6..x
    int dl = __clz((t << 1) | 1u) - 24;       // 0..7
    unsigned t2 = (win >> 6) & 0x7Fu;         // x..x+6
    int dr = __ffs(t2 | 0x80u) - 1;           // 0..7
    int d = dl < dr ? dl : dr;
    return d * d;                              // <= 49
}

// ---------------------------------------------------------------------
// K123 (fully fused): row transform (in smem) + column window + softmax
// + block reduction. Grid: 8 b * 64 ytiles(4 rows) = 512 blocks,
// 256 threads. Row phase: 8 warps x 2 halo rows, register ballots +
// funnel shifts; results live only in smem. Column phase: thread = x.
// Certified exact when windowed min <= 36 (else flag -> exact fallback).
// ---------------------------------------------------------------------
__global__ __launch_bounds__(256) void k123(const float* __restrict__ preds,
                                            const int* __restrict__ tg) {
    int tid = threadIdx.x;
    int lane = tid & 31;
    int wrp = tid >> 5;
    int b = blockIdx.x >> 6;
    int y0 = (blockIdx.x & 63) << 2;

    __shared__ __half2 gs[3][HR][256];   // (P,N) windowed row dist^2, ints
    const __half2 HOOB2 = __float2half2_rn(OOB);

    // ---- row-transform phase: warp w handles halo rows 2w, 2w+1 ----
#pragma unroll
    for (int rr = 0; rr < 2; ++rr) {
        int r = wrp * 2 + rr;
        int gy = y0 - RWIN + r;
        bool valid = (gy >= 0) && (gy < H);       // warp-uniform
        if (valid) {
            int row = b * 256 + gy;
            int tv[8];
#pragma unroll
            for (int c = 0; c < 8; ++c) tv[c] = tg[row * 256 + c * 32 + lane];
#pragma unroll
            for (int cls = 1; cls <= NCLS; ++cls) {
                unsigned bw[8];
#pragma unroll
                for (int c = 0; c < 8; ++c) {
                    bw[c] = __ballot_sync(0xFFFFFFFFu, tv[c] == cls);
                    if (lane == c)
                        d_mask[((cls - 1) * (B * H) + row) * 8 + c] = bw[c];
                }
#pragma unroll
                for (int c = 0; c < 8; ++c) {
                    unsigned bp = (c > 0) ? bw[c - 1] : 0u;
                    unsigned bn = (c < 7) ? bw[c + 1] : 0u;
                    unsigned nbp = (c > 0) ? ~bw[c - 1] : 0u;
                    unsigned nbn = (c < 7) ? ~bw[c + 1] : 0u;
                    unsigned winP, winN;
                    if (lane < RWIN) {
                        winP = __funnelshift_r(bp, bw[c], lane + 32 - RWIN);
                        winN = __funnelshift_r(nbp, ~bw[c], lane + 32 - RWIN);
                    } else {
                        winP = __funnelshift_r(bw[c], bn, lane - RWIN);
                        winN = __funnelshift_r(~bw[c], nbn, lane - RWIN);
                    }
                    int p2 = win_d2_6(winP);
                    int n2 = win_d2_6(winN);
                    gs[cls - 1][r][c * 32 + lane] = __halves2half2(
                        __float2half_rn((float)p2), __float2half_rn((float)n2));
                }
            }
        } else {
#pragma unroll
            for (int cls = 0; cls < 3; ++cls)
#pragma unroll
                for (int c = 0; c < 8; ++c)
                    gs[cls][r][c * 32 + lane] = HOOB2;
        }
    }
    __syncthreads();

    // ---- column phase: thread = x ----
    int x = tid;
    float dmap[3][TY];
    int cnt[3] = {0, 0, 0};

#pragma unroll
    for (int cls = 0; cls < 3; ++cls) {
        __half2 v[HR];
#pragma unroll
        for (int r = 0; r < HR; ++r) v[r] = gs[cls][r][x];
        bool bad = false;
#pragma unroll
        for (int o = 0; o < TY; ++o) {
            __half2 m = v[o + RWIN];
#pragma unroll
            for (int dy = 1; dy <= RWIN; ++dy) {
                __half2 dd = __float2half2_rn((float)(dy * dy));
                m = __hmin2(m, __hadd2(v[o + RWIN - dy], dd));
                m = __hmin2(m, __hadd2(v[o + RWIN + dy], dd));
            }
            float mp = __low2float(m);
            float mn = __high2float(m);
            bad |= (mp > THRESH) || (mn > THRESH);
            bool pos = (__low2float(v[o + RWIN]) == 0.0f);
            dmap[cls][o] = pos ? (1.0f - sqrtf(mn)) : sqrtf(mp);
            cnt[cls] += pos ? 1 : 0;
        }
        if (bad) d_flag[(cls * 8 + b) * W + x] = 1;    // races benign
    }

    // softmax + dot with dmap
    float s[3] = {0.f, 0.f, 0.f};
    const float* pb = preds + b * (4 * IMG) + (y0 << 8) + x;
#pragma unroll
    for (int o = 0; o < TY; ++o) {
        const float* p = pb + (o << 8);
        float e0 = __expf(p[0]);
        float e1 = __expf(p[IMG]);
        float e2 = __expf(p[2 * IMG]);
        float e3 = __expf(p[3 * IMG]);
        float inv = 1.0f / (e0 + e1 + e2 + e3);
        s[0] += dmap[0][o] * (e1 * inv);
        s[1] += dmap[1][o] * (e2 * inv);
        s[2] += dmap[2][o] * (e3 * inv);
    }

    // block reduction
#pragma unroll
    for (int off = 16; off; off >>= 1) {
#pragma unroll
        for (int c = 0; c < 3; ++c) {
            s[c] += __shfl_down_sync(0xFFFFFFFFu, s[c], off);
            cnt[c] += __shfl_down_sync(0xFFFFFFFFu, cnt[c], off);
        }
    }
    __shared__ float sm[8][3];
    __shared__ int smc[8][3];
    if (lane == 0) {
#pragma unroll
        for (int c = 0; c < 3; ++c) { sm[wrp][c] = s[c]; smc[wrp][c] = cnt[c]; }
    }
    __syncthreads();
    if (tid < 3) {
        float t = 0.0f; int ci = 0;
#pragma unroll
        for (int i = 0; i < 8; ++i) { t += sm[i][tid]; ci += smc[i][tid]; }
        d_partial[tid * NBLK2 + blockIdx.x] = t;
        d_cnt[tid * NBLK2 + blockIdx.x] = ci;
    }
}

// ---------------------------------------------------------------------
// Exact reference rowdist (full scans) — fallback only.
// ---------------------------------------------------------------------
__device__ int rowdist_full(const unsigned* m, int x, bool inv) {
    int w = x >> 5, b = x & 31;
    unsigned mw = inv ? ~m[w] : m[w];
    unsigned u = mw & (0xFFFFFFFFu >> (31 - b));
    int dl;
    if (u) {
        dl = b - (31 - __clz(u));
    } else {
        dl = 512 + x + 1;
        for (int i = w - 1; i >= 0; --i) {
            unsigned vi = inv ? ~m[i] : m[i];
            if (vi) { dl = x - (i * 32 + 31 - __clz(vi)); break; }
        }
    }
    unsigned u2 = mw & (0xFFFFFFFFu << b);
    int dr;
    if (u2) {
        dr = (__ffs(u2) - 1) - b;
    } else {
        dr = 512 + 256 - x;
        for (int i = w + 1; i < 8; ++i) {
            unsigned vi = inv ? ~m[i] : m[i];
            if (vi) { dr = i * 32 + (__ffs(vi) - 1) - x; break; }
        }
    }
    return dl < dr ? dl : dr;
}

// ---------------------------------------------------------------------
// Block-cooperative exact fallback for one flagged column (thread = y).
// Exact EDT from stored masks; the approximate path is reconstructed
// bit-exactly from the same masks (funnel-shift window + win_d2_6 ints,
// OOB clamps identical to k123). Deterministic tree-reduced correction.
// ---------------------------------------------------------------------
__device__ void fix_column_coop(int cb, int x, const float* __restrict__ preds,
                                float* adj, float* red) {
    int cls = cb >> 3;      // 0-based
    int b = cb & 7;
    int y = threadIdx.x;
    __shared__ float gpe[256], gne[256], apx[256], anx[256];
    {
        unsigned mw[8];
#pragma unroll
        for (int i = 0; i < 8; ++i)
            mw[i] = d_mask[(cls * (B * H) + b * 256 + y) * 8 + i];
        int dp = rowdist_full(mw, x, false);
        int dn = rowdist_full(mw, x, true);
        gpe[y] = (float)(dp * dp);
        gne[y] = (float)(dn * dn);
        // reconstruct windowed (approximate) row dists exactly as k123
        int s = x - RWIN, idx = s >> 5, off = s & 31;
        unsigned loP = (idx >= 0) ? mw[idx] : 0u;
        unsigned hiP = (idx + 1 < 8) ? mw[idx + 1] : 0u;
        unsigned loN = (idx >= 0) ? ~mw[idx] : 0u;
        unsigned hiN = (idx + 1 < 8) ? ~mw[idx + 1] : 0u;
        unsigned winP = (unsigned)(((((unsigned long long)hiP) << 32) | loP) >> off);
        unsigned winN = (unsigned)(((((unsigned long long)hiN) << 32) | loN) >> off);
        apx[y] = (float)win_d2_6(winP);
        anx[y] = (float)win_d2_6(winN);
    }
    __syncthreads();
    float mpE = 1e30f, mnE = 1e30f;
    for (int yp = 0; yp < 256; ++yp) {
        float dy2 = (float)((y - yp) * (y - yp));
        mpE = fminf(mpE, gpe[yp] + dy2);
        mnE = fminf(mnE, gne[yp] + dy2);
    }
    bool pos = (gpe[y] == 0.0f);
    float exact = pos ? (1.0f - sqrtf(mnE)) : sqrtf(mpE);
    // approximate column min (window +-RWIN, OOB clamps) — replicates k123
    float mpA = 1e30f, mnA = 1e30f;
#pragma unroll
    for (int dy = -RWIN; dy <= RWIN; ++dy) {
        int gy = y + dy;
        float Sp = OOB, Sn = OOB;
        if (gy >= 0 && gy < H) { Sp = apx[gy]; Sn = anx[gy]; }
        float d2 = (float)(dy * dy);
        mpA = fminf(mpA, Sp + d2);
        mnA = fminf(mnA, Sn + d2);
    }
    float approx = pos ? (1.0f - sqrtf(mnA)) : sqrtf(mpA);
    float delta = 0.0f;
    if (exact != approx) {
        const float* p = preds + b * (4 * IMG) + (y << 8) + x;
        float e0 = __expf(p[0]);
        float e1 = __expf(p[IMG]);
        float e2 = __expf(p[2 * IMG]);
        float e3 = __expf(p[3 * IMG]);
        float inv = 1.0f / (e0 + e1 + e2 + e3);
        float pr = ((cls == 0) ? e1 : (cls == 1) ? e2 : e3) * inv;
        delta = (exact - approx) * pr;
    }
    __syncthreads();
    red[y] = delta;
    __syncthreads();
    for (int st = 128; st; st >>= 1) {
        if (y < st) red[y] += red[y + st];
        __syncthreads();
    }
    if (y == 0) adj[cls] += red[0];
    __syncthreads();
}

// ---------------------------------------------------------------------
// K4: final deterministic reduction + fallback corrections + has/count.
// Clears d_flag after consuming it (it is only set in k123, so the
// cleared state is what the next replay must start from).
// ---------------------------------------------------------------------
__global__ __launch_bounds__(256) void k4_final(const float* __restrict__ preds,
                                                float* __restrict__ out) {
    __shared__ float red[256];
    __shared__ float tot[3];
    __shared__ float ccnt[3];
    __shared__ int flagged;
    __shared__ float adj[3];
    int tid = threadIdx.x;
    for (int q = 0; q < 3; ++q) {
        red[tid] = d_partial[q * NBLK2 + tid] + d_partial[q * NBLK2 + 256 + tid];
        __syncthreads();
        for (int st = 128; st; st >>= 1) {
            if (tid < st) red[tid] += red[tid + st];
            __syncthreads();
        }
        if (tid == 0) tot[q] = red[0];
        __syncthreads();
    }
    for (int q = 0; q < 3; ++q) {
        red[tid] = (float)(d_cnt[q * NBLK2 + tid] + d_cnt[q * NBLK2 + 256 + tid]);
        __syncthreads();
        for (int st = 128; st; st >>= 1) {
            if (tid < st) red[tid] += red[tid + st];
            __syncthreads();
        }
        if (tid == 0) ccnt[q] = red[0];
        __syncthreads();
    }
    if (tid == 0) { flagged = 0; adj[0] = adj[1] = adj[2] = 0.0f; }
    __syncthreads();
    int f = 0;
    for (int i = tid; i < NCB * W; i += 256) f |= d_flag[i];
    if (f) atomicOr(&flagged, 1);
    __syncthreads();
    if (flagged) {
        for (int i = 0; i < NCB * W; ++i) {
            if (d_flag[i]) fix_column_coop(i >> 8, i & 255, preds, adj, red);
        }
    }
    __syncthreads();
    // consume-then-clear: next replay starts from all-zero flags
    for (int i = tid; i < NCB * W; i += 256) d_flag[i] = 0;
    if (tid == 0) {
        float total = 0.0f, count = 0.0f;
        for (int c = 0; c < 3; ++c) {
            if (ccnt[c] > 0.0f) {
                total += (tot[c] + adj[c]) * (1.0f / (float)NPIX);
                count += 1.0f;
            }
        }
        out[0] = (count > 0.0f) ? (total / count) : 0.0f;
    }
}

extern "C" void kernel_launch(void* const* d_in, const int* in_sizes, int n_in,
                              void* d_out, int out_size) {
    const float* preds = (const float*)d_in[0];
    const int* targets = (const int*)d_in[1];
    float* out = (float*)d_out;

    k123<<<NBLK2, 256>>>(preds, targets);
    k4_final<<<1, 256>>>(preds, out);
}

// round 8
// speedup vs baseline: 1.1778x; 1.1778x over previous
#include <cuda_runtime.h>
#include <cuda_fp16.h>
#include <math.h>

// Problem constants: preds [8,4,256,256] f32, targets [8,256,256] i32.
#define B 8
#define H 256
#define W 256
#define NCLS 3              // classes 1..3
#define NCB 24              // cb = (cls-1)*8 + b
#define IMG 65536           // H*W
#define NPIX 524288         // B*H*W
#define RWIN 6              // window radius; certified exact when min <= 36
#define THRESH 36.0f
#define OOB 49.0f           // out-of-window / out-of-bounds distance^2 (>36)
#define TY 4                // rows of output per block
#define HR (TY + 2 * RWIN)  // halo rows per block = 16
#define NBLK2 512           // fused-kernel block count (8 b * 64 ytiles)

// -------- scratch (__device__ globals; no runtime allocation) --------
__device__ unsigned d_mask[NCLS * B * H * 8];  // row bitmasks (exact fallback)
__device__ int   d_flag[NCB * W];    // per (cb, x): window not certified
__device__ float d_partial[3 * NBLK2];
__device__ int   d_cnt[3 * NBLK2];

// ---------------------------------------------------------------------
// Branchless windowed nearest-set-bit distance^2 (radius 6).
// win bits 0..12 correspond to positions x-6 .. x+6 (bit 6 = x).
// Exact for d <= 6, else 49 (>36, never enters a certified min).
// ---------------------------------------------------------------------
__device__ __forceinline__ int win_d2_6(unsigned win) {
    unsigned t = win & 0x7Fu;                 // x-6..x
    int dl = __clz((t << 1) | 1u) - 24;       // 0..7
    unsigned t2 = (win >> 6) & 0x7Fu;         // x..x+6
    int dr = __ffs(t2 | 0x80u) - 1;           // 0..7
    int d = dl < dr ? dl : dr;
    return d * d;                              // <= 49
}

// ---------------------------------------------------------------------
// K123 (fully fused): row transform (in smem) + column window + softmax
// + block reduction. Grid: 8 b * 64 ytiles(4 rows) = 512 blocks,
// 256 threads. Row phase: 8 warps x 2 halo rows, register ballots +
// funnel shifts, ONE nearest-opposite window eval per pixel/class.
// Column phase: thread = x. Certified exact when windowed min <= 36
// (else flag -> exact fallback in k4).
// ---------------------------------------------------------------------
__global__ __launch_bounds__(256) void k123(const float* __restrict__ preds,
                                            const int* __restrict__ tg) {
    int tid = threadIdx.x;
    int lane = tid & 31;
    int wrp = tid >> 5;
    int b = blockIdx.x >> 6;
    int y0 = (blockIdx.x & 63) << 2;

    __shared__ __half2 gs[3][HR][256];   // (P,N) windowed row dist^2, ints
    const __half2 HOOB2 = __float2half2_rn(OOB);

    // validity masks per chunk (x-edge bits outside [0,255] must be 0)
    unsigned vm[8];
#pragma unroll
    for (int c = 0; c < 8; ++c) {
        int x = c * 32 + lane;
        unsigned v = 0x1FFFu;
        if (x < RWIN) v = (v << (RWIN - x)) & 0x1FFFu;
        if (x > 255 - RWIN) v >>= (x - (255 - RWIN));
        vm[c] = v;
    }

    // ---- row-transform phase: warp w handles halo rows 2w, 2w+1 ----
#pragma unroll
    for (int rr = 0; rr < 2; ++rr) {
        int r = wrp * 2 + rr;
        int gy = y0 - RWIN + r;
        bool valid = (gy >= 0) && (gy < H);       // warp-uniform
        if (valid) {
            int row = b * 256 + gy;
            int tv[8];
#pragma unroll
            for (int c = 0; c < 8; ++c) tv[c] = tg[row * 256 + c * 32 + lane];
#pragma unroll
            for (int cls = 1; cls <= NCLS; ++cls) {
                unsigned bw[8];
#pragma unroll
                for (int c = 0; c < 8; ++c) {
                    bw[c] = __ballot_sync(0xFFFFFFFFu, tv[c] == cls);
                    if (lane == c)
                        d_mask[((cls - 1) * (B * H) + row) * 8 + c] = bw[c];
                }
#pragma unroll
                for (int c = 0; c < 8; ++c) {
                    unsigned bp = (c > 0) ? bw[c - 1] : 0u;
                    unsigned bn = (c < 7) ? bw[c + 1] : 0u;
                    unsigned winP;
                    if (lane < RWIN)
                        winP = __funnelshift_r(bp, bw[c], lane + 32 - RWIN);
                    else
                        winP = __funnelshift_r(bw[c], bn, lane - RWIN);
                    bool own = (winP >> RWIN) & 1u;   // this pixel is pos
                    unsigned winX = (own ? ~winP : winP) & vm[c];
                    float e2 = (float)win_d2_6(winX); // dist^2 to opposite
                    __half he = __float2half_rn(e2);
                    __half hz = __float2half_rn(0.0f);
                    gs[cls - 1][r][c * 32 + lane] =
                        own ? __halves2half2(hz, he) : __halves2half2(he, hz);
                }
            }
        } else {
#pragma unroll
            for (int cls = 0; cls < 3; ++cls)
#pragma unroll
                for (int c = 0; c < 8; ++c)
                    gs[cls][r][c * 32 + lane] = HOOB2;
        }
    }
    __syncthreads();

    // ---- column phase: thread = x ----
    int x = tid;
    float dmap[3][TY];
    int cnt[3] = {0, 0, 0};

#pragma unroll
    for (int cls = 0; cls < 3; ++cls) {
        __half2 v[HR];
#pragma unroll
        for (int r = 0; r < HR; ++r) v[r] = gs[cls][r][x];
        bool bad = false;
#pragma unroll
        for (int o = 0; o < TY; ++o) {
            __half2 m = v[o + RWIN];
#pragma unroll
            for (int dy = 1; dy <= RWIN; ++dy) {
                __half2 dd = __float2half2_rn((float)(dy * dy));
                m = __hmin2(m, __hadd2(v[o + RWIN - dy], dd));
                m = __hmin2(m, __hadd2(v[o + RWIN + dy], dd));
            }
            float mp = __low2float(m);
            float mn = __high2float(m);
            bad |= (mp > THRESH) || (mn > THRESH);
            bool pos = (__low2float(v[o + RWIN]) == 0.0f);
            dmap[cls][o] = pos ? (1.0f - sqrtf(mn)) : sqrtf(mp);
            cnt[cls] += pos ? 1 : 0;
        }
        if (bad) d_flag[(cls * 8 + b) * W + x] = 1;    // races benign
    }

    // softmax + dot with dmap
    float s[3] = {0.f, 0.f, 0.f};
    const float* pb = preds + b * (4 * IMG) + (y0 << 8) + x;
#pragma unroll
    for (int o = 0; o < TY; ++o) {
        const float* p = pb + (o << 8);
        float e0 = __expf(p[0]);
        float e1 = __expf(p[IMG]);
        float e2 = __expf(p[2 * IMG]);
        float e3 = __expf(p[3 * IMG]);
        float inv = 1.0f / (e0 + e1 + e2 + e3);
        s[0] += dmap[0][o] * (e1 * inv);
        s[1] += dmap[1][o] * (e2 * inv);
        s[2] += dmap[2][o] * (e3 * inv);
    }

    // block reduction
#pragma unroll
    for (int off = 16; off; off >>= 1) {
#pragma unroll
        for (int c = 0; c < 3; ++c) {
            s[c] += __shfl_down_sync(0xFFFFFFFFu, s[c], off);
            cnt[c] += __shfl_down_sync(0xFFFFFFFFu, cnt[c], off);
        }
    }
    __shared__ float sm[8][3];
    __shared__ int smc[8][3];
    if (lane == 0) {
#pragma unroll
        for (int c = 0; c < 3; ++c) { sm[wrp][c] = s[c]; smc[wrp][c] = cnt[c]; }
    }
    __syncthreads();
    if (tid < 3) {
        float t = 0.0f; int ci = 0;
#pragma unroll
        for (int i = 0; i < 8; ++i) { t += sm[i][tid]; ci += smc[i][tid]; }
        d_partial[tid * NBLK2 + blockIdx.x] = t;
        d_cnt[tid * NBLK2 + blockIdx.x] = ci;
    }
}

// ---------------------------------------------------------------------
// Exact reference rowdist (full scans) — fallback only.
// ---------------------------------------------------------------------
__device__ int rowdist_full(const unsigned* m, int x, bool inv) {
    int w = x >> 5, b = x & 31;
    unsigned mw = inv ? ~m[w] : m[w];
    unsigned u = mw & (0xFFFFFFFFu >> (31 - b));
    int dl;
    if (u) {
        dl = b - (31 - __clz(u));
    } else {
        dl = 512 + x + 1;
        for (int i = w - 1; i >= 0; --i) {
            unsigned vi = inv ? ~m[i] : m[i];
            if (vi) { dl = x - (i * 32 + 31 - __clz(vi)); break; }
        }
    }
    unsigned u2 = mw & (0xFFFFFFFFu << b);
    int dr;
    if (u2) {
        dr = (__ffs(u2) - 1) - b;
    } else {
        dr = 512 + 256 - x;
        for (int i = w + 1; i < 8; ++i) {
            unsigned vi = inv ? ~m[i] : m[i];
            if (vi) { dr = i * 32 + (__ffs(vi) - 1) - x; break; }
        }
    }
    return dl < dr ? dl : dr;
}

// ---------------------------------------------------------------------
// Block-cooperative exact fallback for one flagged column (thread = y).
// Exact EDT from stored masks; the approximate path is reconstructed
// bit-exactly (two-window form yields identical values to the
// nearest-opposite form used in k123). Deterministic tree reduce.
// ---------------------------------------------------------------------
__device__ void fix_column_coop(int cb, int x, const float* __restrict__ preds,
                                float* adj, float* red) {
    int cls = cb >> 3;      // 0-based
    int b = cb & 7;
    int y = threadIdx.x;
    __shared__ float gpe[256], gne[256], apx[256], anx[256];
    {
        unsigned mw[8];
#pragma unroll
        for (int i = 0; i < 8; ++i)
            mw[i] = d_mask[(cls * (B * H) + b * 256 + y) * 8 + i];
        int dp = rowdist_full(mw, x, false);
        int dn = rowdist_full(mw, x, true);
        gpe[y] = (float)(dp * dp);
        gne[y] = (float)(dn * dn);
        // reconstruct windowed (approximate) row dists exactly as k123
        int s = x - RWIN, idx = s >> 5, off = s & 31;
        unsigned loP = (idx >= 0) ? mw[idx] : 0u;
        unsigned hiP = (idx + 1 < 8) ? mw[idx + 1] : 0u;
        unsigned loN = (idx >= 0) ? ~mw[idx] : 0u;
        unsigned hiN = (idx + 1 < 8) ? ~mw[idx + 1] : 0u;
        unsigned winP = (unsigned)(((((unsigned long long)hiP) << 32) | loP) >> off);
        unsigned winN = (unsigned)(((((unsigned long long)hiN) << 32) | loN) >> off);
        unsigned vmv = 0x1FFFu;
        if (x < RWIN) vmv = (vmv << (RWIN - x)) & 0x1FFFu;
        if (x > 255 - RWIN) vmv >>= (x - (255 - RWIN));
        apx[y] = (float)win_d2_6(winP & vmv);
        anx[y] = (float)win_d2_6(winN & vmv);
    }
    __syncthreads();
    float mpE = 1e30f, mnE = 1e30f;
    for (int yp = 0; yp < 256; ++yp) {
        float dy2 = (float)((y - yp) * (y - yp));
        mpE = fminf(mpE, gpe[yp] + dy2);
        mnE = fminf(mnE, gne[yp] + dy2);
    }
    bool pos = (gpe[y] == 0.0f);
    float exact = pos ? (1.0f - sqrtf(mnE)) : sqrtf(mpE);
    // approximate column min (window +-RWIN, OOB clamps) — replicates k123
    float mpA = 1e30f, mnA = 1e30f;
#pragma unroll
    for (int dy = -RWIN; dy <= RWIN; ++dy) {
        int gy = y + dy;
        float Sp = OOB, Sn = OOB;
        if (gy >= 0 && gy < H) { Sp = apx[gy]; Sn = anx[gy]; }
        float d2 = (float)(dy * dy);
        mpA = fminf(mpA, Sp + d2);
        mnA = fminf(mnA, Sn + d2);
    }
    float approx = pos ? (1.0f - sqrtf(mnA)) : sqrtf(mpA);
    float delta = 0.0f;
    if (exact != approx) {
        const float* p = preds + b * (4 * IMG) + (y << 8) + x;
        float e0 = __expf(p[0]);
        float e1 = __expf(p[IMG]);
        float e2 = __expf(p[2 * IMG]);
        float e3 = __expf(p[3 * IMG]);
        float inv = 1.0f / (e0 + e1 + e2 + e3);
        float pr = ((cls == 0) ? e1 : (cls == 1) ? e2 : e3) * inv;
        delta = (exact - approx) * pr;
    }
    __syncthreads();
    red[y] = delta;
    __syncthreads();
    for (int st = 128; st; st >>= 1) {
        if (y < st) red[y] += red[y + st];
        __syncthreads();
    }
    if (y == 0) adj[cls] += red[0];
    __syncthreads();
}

// ---------------------------------------------------------------------
// K4: warp-parallel final reduction. Warps 0-5 each reduce one quantity
// (3 sums + 3 counts) with coalesced strided loads + shuffles; warps 6-7
// scan the flag array concurrently. 2 barriers on the fast path.
// Clears d_flag after consuming it.
// ---------------------------------------------------------------------
__global__ __launch_bounds__(256) void k4_final(const float* __restrict__ preds,
                                                float* __restrict__ out) {
    __shared__ float val[6];
    __shared__ int flg;
    __shared__ float adj[3];
    __shared__ float red[256];
    int tid = threadIdx.x;
    int w = tid >> 5, lane = tid & 31;
    if (tid == 0) flg = 0;
    if (tid < 3) adj[tid] = 0.0f;
    __syncthreads();
    if (w < 6) {
        float s = 0.0f;
        if (w < 3) {
#pragma unroll
            for (int i = lane; i < NBLK2; i += 32) s += d_partial[w * NBLK2 + i];
        } else {
#pragma unroll
            for (int i = lane; i < NBLK2; i += 32)
                s += (float)d_cnt[(w - 3) * NBLK2 + i];
        }
#pragma unroll
        for (int o = 16; o; o >>= 1) s += __shfl_down_sync(0xFFFFFFFFu, s, o);
        if (lane == 0) val[w] = s;
    } else {
        int t = tid - 192, f = 0;
        for (int i = t; i < NCB * W; i += 64) f |= d_flag[i];
        if (f) atomicOr(&flg, 1);
    }
    __syncthreads();
    if (flg) {                        // block-uniform; never on typical inputs
        for (int i = 0; i < NCB * W; ++i) {
            if (d_flag[i]) fix_column_coop(i >> 8, i & 255, preds, adj, red);
        }
    }
    __syncthreads();
    // consume-then-clear: next replay starts from all-zero flags
    for (int i = tid; i < NCB * W; i += 256) d_flag[i] = 0;
    if (tid == 0) {
        float total = 0.0f, count = 0.0f;
        for (int c = 0; c < 3; ++c) {
            if (val[3 + c] > 0.0f) {
                total += (val[c] + adj[c]) * (1.0f / (float)NPIX);
                count += 1.0f;
            }
        }
        out[0] = (count > 0.0f) ? (total / count) : 0.0f;
    }
}

extern "C" void kernel_launch(void* const* d_in, const int* in_sizes, int n_in,
                              void* d_out, int out_size) {
    const float* preds = (const float*)d_in[0];
    const int* targets = (const int*)d_in[1];
    float* out = (float*)d_out;

    k123<<<NBLK2, 256>>>(preds, targets);
    k4_final<<<1, 256>>>(preds, out);
}

// round 9
// speedup vs baseline: 1.2790x; 1.0860x over previous
#include <cuda_runtime.h>
#include <cuda_fp16.h>
#include <math.h>

// Problem constants: preds [8,4,256,256] f32, targets [8,256,256] i32.
#define B 8
#define H 256
#define W 256
#define NCLS 3              // classes 1..3
#define NCB 24              // cb = (cls-1)*8 + b
#define IMG 65536           // H*W
#define NPIX 524288         // B*H*W
#define RWIN 6              // window radius; certified exact when min <= 36
#define THRESH 36.0f
#define OOB 49.0f           // out-of-window / out-of-bounds distance^2 (>36)
#define TY 8                // rows of output per block
#define HR (TY + 2 * RWIN)  // halo rows per block = 20
#define NBLK 256            // 8 b * 32 ytiles
#define FPSCALE 4294967296.0   // 2^32 fixed-point scale

// -------- scratch (__device__ globals; zero-initialized) --------
__device__ unsigned d_mask[NCLS * B * H * 8];  // row bitmasks (exact fallback)
__device__ int   d_flag[NCB * W];    // per (cb, x): window not certified
__device__ long long d_sumll[3];     // fixed-point class sums (deterministic)
__device__ int   d_cntg[3];          // class pos counts
__device__ int   d_ctr;              // completed-block counter

// ---------------------------------------------------------------------
// Branchless windowed nearest-set-bit distance^2 (radius 6).
// win bits 0..12 correspond to positions x-6 .. x+6 (bit 6 = x).
// Exact for d <= 6, else 49 (>36, never enters a certified min).
// ---------------------------------------------------------------------
__device__ __forceinline__ int win_d2_6(unsigned win) {
    unsigned t = win & 0x7Fu;                 // x-6..x
    int dl = __clz((t << 1) | 1u) - 24;       // 0..7
    unsigned t2 = (win >> 6) & 0x7Fu;         // x..x+6
    int dr = __ffs(t2 | 0x80u) - 1;           // 0..7
    int d = dl < dr ? dl : dr;
    return d * d;                              // <= 49
}

// ---------------------------------------------------------------------
// Exact reference rowdist (full scans) — fallback only.
// ---------------------------------------------------------------------
__device__ int rowdist_full(const unsigned* m, int x, bool inv) {
    int w = x >> 5, b = x & 31;
    unsigned mw = inv ? ~m[w] : m[w];
    unsigned u = mw & (0xFFFFFFFFu >> (31 - b));
    int dl;
    if (u) {
        dl = b - (31 - __clz(u));
    } else {
        dl = 512 + x + 1;
        for (int i = w - 1; i >= 0; --i) {
            unsigned vi = inv ? ~m[i] : m[i];
            if (vi) { dl = x - (i * 32 + 31 - __clz(vi)); break; }
        }
    }
    unsigned u2 = mw & (0xFFFFFFFFu << b);
    int dr;
    if (u2) {
        dr = (__ffs(u2) - 1) - b;
    } else {
        dr = 512 + 256 - x;
        for (int i = w + 1; i < 8; ++i) {
            unsigned vi = inv ? ~m[i] : m[i];
            if (vi) { dr = i * 32 + (__ffs(vi) - 1) - x; break; }
        }
    }
    return dl < dr ? dl : dr;
}

// ---------------------------------------------------------------------
// Block-cooperative exact fallback for one flagged column (thread = y).
// Exact EDT from stored masks; the approximate path is reconstructed
// bit-exactly from the same masks (identical values to the
// nearest-opposite form in the main pass). Deterministic tree reduce.
// Never executes on typical inputs.
// ---------------------------------------------------------------------
__device__ void fix_column_coop(int cb, int x, const float* __restrict__ preds,
                                float* adj, float* red) {
    int cls = cb >> 3;      // 0-based
    int b = cb & 7;
    int y = threadIdx.x;
    __shared__ float gpe[256], gne[256], apx[256], anx[256];
    {
        unsigned mw[8];
#pragma unroll
        for (int i = 0; i < 8; ++i)
            mw[i] = d_mask[(cls * (B * H) + b * 256 + y) * 8 + i];
        int dp = rowdist_full(mw, x, false);
        int dn = rowdist_full(mw, x, true);
        gpe[y] = (float)(dp * dp);
        gne[y] = (float)(dn * dn);
        // reconstruct windowed (approximate) row dists exactly
        int s = x - RWIN, idx = s >> 5, off = s & 31;
        unsigned loP = (idx >= 0) ? mw[idx] : 0u;
        unsigned hiP = (idx + 1 < 8) ? mw[idx + 1] : 0u;
        unsigned loN = (idx >= 0) ? ~mw[idx] : 0u;
        unsigned hiN = (idx + 1 < 8) ? ~mw[idx + 1] : 0u;
        unsigned winP = (unsigned)(((((unsigned long long)hiP) << 32) | loP) >> off);
        unsigned winN = (unsigned)(((((unsigned long long)hiN) << 32) | loN) >> off);
        unsigned vmv = 0x1FFFu;
        if (x < RWIN) vmv = (vmv << (RWIN - x)) & 0x1FFFu;
        if (x > 255 - RWIN) vmv >>= (x - (255 - RWIN));
        apx[y] = (float)win_d2_6(winP & vmv);
        anx[y] = (float)win_d2_6(winN & vmv);
    }
    __syncthreads();
    float mpE = 1e30f, mnE = 1e30f;
    for (int yp = 0; yp < 256; ++yp) {
        float dy2 = (float)((y - yp) * (y - yp));
        mpE = fminf(mpE, gpe[yp] + dy2);
        mnE = fminf(mnE, gne[yp] + dy2);
    }
    bool pos = (gpe[y] == 0.0f);
    float exact = pos ? (1.0f - sqrtf(mnE)) : sqrtf(mpE);
    // approximate column min (window +-RWIN, OOB clamps)
    float mpA = 1e30f, mnA = 1e30f;
#pragma unroll
    for (int dy = -RWIN; dy <= RWIN; ++dy) {
        int gy = y + dy;
        float Sp = OOB, Sn = OOB;
        if (gy >= 0 && gy < H) { Sp = apx[gy]; Sn = anx[gy]; }
        float d2 = (float)(dy * dy);
        mpA = fminf(mpA, Sp + d2);
        mnA = fminf(mnA, Sn + d2);
    }
    float approx = pos ? (1.0f - sqrtf(mnA)) : sqrtf(mpA);
    float delta = 0.0f;
    if (exact != approx) {
        const float* p = preds + b * (4 * IMG) + (y << 8) + x;
        float e0 = __expf(p[0]);
        float e1 = __expf(p[IMG]);
        float e2 = __expf(p[2 * IMG]);
        float e3 = __expf(p[3 * IMG]);
        float inv = 1.0f / (e0 + e1 + e2 + e3);
        float pr = ((cls == 0) ? e1 : (cls == 1) ? e2 : e3) * inv;
        delta = (exact - approx) * pr;
    }
    __syncthreads();
    red[y] = delta;
    __syncthreads();
    for (int st = 128; st; st >>= 1) {
        if (y < st) red[y] += red[y + st];
        __syncthreads();
    }
    if (y == 0) adj[cls] += red[0];
    __syncthreads();
}

// ---------------------------------------------------------------------
// KALL: the whole problem in one kernel.
// Grid: 8 b * 32 ytiles(8 rows) = 256 blocks, 256 threads.
// Per class: row transform into smem (8 warps x up-to-3 halo rows,
// register ballots + funnel shifts, nearest-opposite window), then
// column window (thread = x). Then softmax + block reduce + global
// integer atomics; the last block finalizes (fallback, has/count,
// output, state reset for the next graph replay).
// ---------------------------------------------------------------------
__global__ __launch_bounds__(256) void kall(const float* __restrict__ preds,
                                            const int* __restrict__ tg,
                                            float* __restrict__ out) {
    int tid = threadIdx.x;
    int lane = tid & 31;
    int wrp = tid >> 5;
    int b = blockIdx.x >> 5;
    int y0 = (blockIdx.x & 31) << 3;

    __shared__ __half2 gs[HR][256];   // (P,N) windowed row dist^2, one class
    __shared__ float sm[8][3];
    __shared__ int smc[8][3];
    __shared__ float red[256];
    __shared__ float adj[3];
    __shared__ int sh_flagged;
    __shared__ int sh_last;
    const __half2 HOOB2 = __float2half2_rn(OOB);

    // validity masks per chunk (x-edge bits outside [0,255] must be 0)
    unsigned vm[8];
#pragma unroll
    for (int c = 0; c < 8; ++c) {
        int x = c * 32 + lane;
        unsigned v = 0x1FFFu;
        if (x < RWIN) v = (v << (RWIN - x)) & 0x1FFFu;
        if (x > 255 - RWIN) v >>= (x - (255 - RWIN));
        vm[c] = v;
    }

    // load targets for this warp's halo rows (r = wrp, wrp+8, wrp+16)
    int tv[3][8];
    bool val[3];
#pragma unroll
    for (int k = 0; k < 3; ++k) {
        int r = wrp + 8 * k;
        val[k] = false;
        if (r < HR) {
            int gy = y0 - RWIN + r;
            if (gy >= 0 && gy < H) {
                val[k] = true;
                int row = b * 256 + gy;
#pragma unroll
                for (int c = 0; c < 8; ++c) tv[k][c] = tg[row * 256 + c * 32 + lane];
            }
        }
    }

    float dmap[3][TY];
    int cnt[3] = {0, 0, 0};
    bool bad[3] = {false, false, false};

#pragma unroll
    for (int cls = 0; cls < 3; ++cls) {
        // ---- row phase ----
#pragma unroll
        for (int k = 0; k < 3; ++k) {
            int r = wrp + 8 * k;
            if (r < HR) {                          // warp-uniform
                if (val[k]) {                      // warp-uniform
                    int row = b * 256 + (y0 - RWIN + r);
                    unsigned bw[8];
#pragma unroll
                    for (int c = 0; c < 8; ++c) {
                        bw[c] = __ballot_sync(0xFFFFFFFFu, tv[k][c] == cls + 1);
                        if (lane == c)
                            d_mask[(cls * (B * H) + row) * 8 + c] = bw[c];
                    }
#pragma unroll
                    for (int c = 0; c < 8; ++c) {
                        unsigned bp = (c > 0) ? bw[c - 1] : 0u;
                        unsigned bn = (c < 7) ? bw[c + 1] : 0u;
                        unsigned winP;
                        if (lane < RWIN)
                            winP = __funnelshift_r(bp, bw[c], lane + 32 - RWIN);
                        else
                            winP = __funnelshift_r(bw[c], bn, lane - RWIN);
                        bool own = (winP >> RWIN) & 1u;
                        unsigned winX = (own ? ~winP : winP) & vm[c];
                        float e2 = (float)win_d2_6(winX);
                        __half he = __float2half_rn(e2);
                        __half hz = __float2half_rn(0.0f);
                        gs[r][c * 32 + lane] =
                            own ? __halves2half2(hz, he) : __halves2half2(he, hz);
                    }
                } else {
#pragma unroll
                    for (int c = 0; c < 8; ++c) gs[r][c * 32 + lane] = HOOB2;
                }
            }
        }
        __syncthreads();

        // ---- column phase: thread = x ----
        __half2 v[HR];
#pragma unroll
        for (int r = 0; r < HR; ++r) v[r] = gs[r][tid];
#pragma unroll
        for (int o = 0; o < TY; ++o) {
            __half2 m = v[o + RWIN];
#pragma unroll
            for (int dy = 1; dy <= RWIN; ++dy) {
                __half2 dd = __float2half2_rn((float)(dy * dy));
                m = __hmin2(m, __hadd2(v[o + RWIN - dy], dd));
                m = __hmin2(m, __hadd2(v[o + RWIN + dy], dd));
            }
            float mp = __low2float(m);
            float mn = __high2float(m);
            bad[cls] |= (mp > THRESH) || (mn > THRESH);
            bool pos = (__low2float(v[o + RWIN]) == 0.0f);
            dmap[cls][o] = pos ? (1.0f - sqrtf(mn)) : sqrtf(mp);
            cnt[cls] += pos ? 1 : 0;
        }
        __syncthreads();   // before next class overwrites gs
    }
#pragma unroll
    for (int c = 0; c < 3; ++c)
        if (bad[c]) d_flag[(c * 8 + b) * W + tid] = 1;   // races benign

    // ---- softmax + dot with dmap ----
    float s[3] = {0.f, 0.f, 0.f};
    const float* pb = preds + b * (4 * IMG) + (y0 << 8) + tid;
#pragma unroll
    for (int o = 0; o < TY; ++o) {
        const float* p = pb + (o << 8);
        float e0 = __expf(p[0]);
        float e1 = __expf(p[IMG]);
        float e2 = __expf(p[2 * IMG]);
        float e3 = __expf(p[3 * IMG]);
        float inv = 1.0f / (e0 + e1 + e2 + e3);
        s[0] += dmap[0][o] * (e1 * inv);
        s[1] += dmap[1][o] * (e2 * inv);
        s[2] += dmap[2][o] * (e3 * inv);
    }

    // ---- block reduction ----
#pragma unroll
    for (int off = 16; off; off >>= 1) {
#pragma unroll
        for (int c = 0; c < 3; ++c) {
            s[c] += __shfl_down_sync(0xFFFFFFFFu, s[c], off);
            cnt[c] += __shfl_down_sync(0xFFFFFFFFu, cnt[c], off);
        }
    }
    if (lane == 0) {
#pragma unroll
        for (int c = 0; c < 3; ++c) { sm[wrp][c] = s[c]; smc[wrp][c] = cnt[c]; }
    }
    __syncthreads();
    if (tid < 3) {
        float t = 0.0f; int ci = 0;
#pragma unroll
        for (int i = 0; i < 8; ++i) { t += sm[i][tid]; ci += smc[i][tid]; }
        long long q = __double2ll_rn((double)t * FPSCALE);
        atomicAdd((unsigned long long*)&d_sumll[tid], (unsigned long long)q);
        atomicAdd(&d_cntg[tid], ci);
    }
    __syncthreads();
    if (tid == 0) {
        __threadfence();
        sh_last = (atomicAdd(&d_ctr, 1) == NBLK - 1) ? 1 : 0;
    }
    __syncthreads();
    if (!sh_last) return;

    // ================= last block: finalize =================
    if (tid == 0) sh_flagged = 0;
    if (tid < 3) adj[tid] = 0.0f;
    __syncthreads();
    {
        int f = 0;
        for (int i = tid; i < NCB * W; i += 256) f |= d_flag[i];
        if (f) atomicOr(&sh_flagged, 1);
    }
    __syncthreads();
    if (sh_flagged) {                  // block-uniform; never on typical inputs
        for (int i = 0; i < NCB * W; ++i) {
            if (d_flag[i]) fix_column_coop(i >> 8, i & 255, preds, adj, red);
        }
    }
    __syncthreads();
    // consume-then-clear flags for the next graph replay
    for (int i = tid; i < NCB * W; i += 256) d_flag[i] = 0;
    if (tid == 0) {
        float total = 0.0f, count = 0.0f;
        for (int c = 0; c < 3; ++c) {
            if (d_cntg[c] > 0) {
                float tc = (float)((double)d_sumll[c] / FPSCALE) + adj[c];
                total += tc * (1.0f / (float)NPIX);
                count += 1.0f;
            }
            d_sumll[c] = 0;            // reset state for next replay
            d_cntg[c] = 0;
        }
        d_ctr = 0;
        out[0] = (count > 0.0f) ? (total / count) : 0.0f;
    }
}

extern "C" void kernel_launch(void* const* d_in, const int* in_sizes, int n_in,
                              void* d_out, int out_size) {
    const float* preds = (const float*)d_in[0];
    const int* targets = (const int*)d_in[1];
    float* out = (float*)d_out;

    kall<<<NBLK, 256>>>(preds, targets, out);
}